// round 3
// baseline (speedup 1.0000x reference)
#include <cuda_runtime.h>

#define Bz 8
#define Cc 512
#define Nn 2048
#define Dd 128
#define INV_SCALE 0.08838834764831845f   // 1/sqrt(128)

// Scratch (allocation-free rule: __device__ globals)
__device__ float g_qk[(size_t)Bz * Dd * Nn];    // [b][d][n]  8 MB
__device__ float g_v [(size_t)Bz * Dd * Nn];    // [b][d][n]  8 MB
__device__ float g_linv[(size_t)Bz * Nn];       // 1 / sum_m exp(e[n,m])

// ---------------------------------------------------------------------------
// Kernel 1: projections. qk[d,n] = wqk[d,:]·x[:,n]; v[d,n] = wv[d,:]·x[:,n]+bv
// Block computes a 64x64 (d x n) tile of BOTH outputs, sharing the x tile.
// ---------------------------------------------------------------------------
__global__ __launch_bounds__(256) void proj_kernel(
    const float* __restrict__ x, const float* __restrict__ wqk,
    const float* __restrict__ wv, const float* __restrict__ bv)
{
    __shared__ float Aq[16][64];   // [k][d]
    __shared__ float Av[16][64];
    __shared__ float Bs[16][64];   // [k][n]
    const int n0 = blockIdx.x * 64;
    const int d0 = blockIdx.y * 64;
    const int b  = blockIdx.z;
    const int tid = threadIdx.x;
    const int tx = tid & 15, ty = tid >> 4;
    const float* xb = x + (size_t)b * Cc * Nn;

    float accq[4][4] = {}, accv[4][4] = {};

    for (int c0 = 0; c0 < Cc; c0 += 16) {
        {   // load W tiles (64x16, transposed into [k][d]) and X tile (16x64)
            int row = tid >> 2, c4 = (tid & 3) * 4;
            float4 a = *(const float4*)&wqk[(d0 + row) * Cc + c0 + c4];
            Aq[c4 + 0][row] = a.x; Aq[c4 + 1][row] = a.y;
            Aq[c4 + 2][row] = a.z; Aq[c4 + 3][row] = a.w;
            float4 v = *(const float4*)&wv[(d0 + row) * Cc + c0 + c4];
            Av[c4 + 0][row] = v.x; Av[c4 + 1][row] = v.y;
            Av[c4 + 2][row] = v.z; Av[c4 + 3][row] = v.w;
            int brow = tid >> 4, bc4 = (tid & 15) * 4;
            *(float4*)&Bs[brow][bc4] =
                *(const float4*)&xb[(c0 + brow) * Nn + n0 + bc4];
        }
        __syncthreads();
        #pragma unroll
        for (int k = 0; k < 16; ++k) {
            float aq[4], av[4];
            #pragma unroll
            for (int r = 0; r < 4; ++r) {
                aq[r] = Aq[k][ty * 4 + r];
                av[r] = Av[k][ty * 4 + r];
            }
            float4 bb = *(const float4*)&Bs[k][tx * 4];
            float bv4[4] = {bb.x, bb.y, bb.z, bb.w};
            #pragma unroll
            for (int r = 0; r < 4; ++r)
                #pragma unroll
                for (int c = 0; c < 4; ++c) {
                    accq[r][c] += aq[r] * bv4[c];
                    accv[r][c] += av[r] * bv4[c];
                }
        }
        __syncthreads();
    }

    #pragma unroll
    for (int r = 0; r < 4; ++r) {
        int d = d0 + ty * 4 + r;
        float bvd = bv[d];
        float4 q = make_float4(accq[r][0], accq[r][1], accq[r][2], accq[r][3]);
        float4 v = make_float4(accv[r][0] + bvd, accv[r][1] + bvd,
                               accv[r][2] + bvd, accv[r][3] + bvd);
        *(float4*)&g_qk[((size_t)b * Dd + d) * Nn + n0 + tx * 4] = q;
        *(float4*)&g_v [((size_t)b * Dd + d) * Nn + n0 + tx * 4] = v;
    }
}

// ---------------------------------------------------------------------------
// Kernel 2: l[n] = sum_m exp( (q_n · q_m) * INV_SCALE ); store 1/l.
// No max-subtraction needed: logits bounded by ~|q|^2/sqrt(D) ~ O(17).
// Block owns 64 rows n (Qn resident, 32KB), streams 64-col m tiles.
// ---------------------------------------------------------------------------
__global__ __launch_bounds__(256) void stats_kernel()
{
    extern __shared__ float sm[];
    float (*Qn)[64] = (float(*)[64])sm;              // [128][64]
    float (*Qm)[64] = (float(*)[64])(sm + Dd * 64);  // [128][64]
    __shared__ float lsum[64];

    const int n0 = blockIdx.x * 64;
    const int b  = blockIdx.y;
    const int tid = threadIdx.x;
    const int tx = tid & 15, ty = tid >> 4;
    const float* qkb = g_qk + (size_t)b * Dd * Nn;

    for (int i = tid; i < Dd * 16; i += 256) {
        int row = i >> 4, c4 = (i & 15) * 4;
        *(float4*)&Qn[row][c4] = *(const float4*)&qkb[row * Nn + n0 + c4];
    }
    if (tid < 64) lsum[tid] = 0.0f;
    float lacc[4] = {0.f, 0.f, 0.f, 0.f};
    __syncthreads();

    for (int m0 = 0; m0 < Nn; m0 += 64) {
        for (int i = tid; i < Dd * 16; i += 256) {
            int row = i >> 4, c4 = (i & 15) * 4;
            *(float4*)&Qm[row][c4] = *(const float4*)&qkb[row * Nn + m0 + c4];
        }
        __syncthreads();

        float acc[4][4] = {};
        #pragma unroll 8
        for (int k = 0; k < Dd; ++k) {
            float a[4];
            #pragma unroll
            for (int r = 0; r < 4; ++r) a[r] = Qn[k][ty * 4 + r];
            float4 bb = *(const float4*)&Qm[k][tx * 4];
            float bv4[4] = {bb.x, bb.y, bb.z, bb.w};
            #pragma unroll
            for (int r = 0; r < 4; ++r)
                #pragma unroll
                for (int c = 0; c < 4; ++c) acc[r][c] += a[r] * bv4[c];
        }
        #pragma unroll
        for (int r = 0; r < 4; ++r)
            #pragma unroll
            for (int c = 0; c < 4; ++c)
                lacc[r] += __expf(acc[r][c] * INV_SCALE);
        __syncthreads();
    }

    #pragma unroll
    for (int r = 0; r < 4; ++r) atomicAdd(&lsum[ty * 4 + r], lacc[r]);
    __syncthreads();
    if (tid < 64)
        g_linv[(size_t)b * Nn + n0 + tid] = 1.0f / lsum[tid];
}

// ---------------------------------------------------------------------------
// Kernel 3: out[d,m] = sum_n v[d,n] * exp(e[n,m])*linv[n].
// Block owns a 64-wide m tile and all 128 d rows; loops over n tiles:
//   Phase A: e tile (recompute, GEMM 64x64x128) -> P in smem
//   Phase B: O[128x64] += V[128x64tile] @ P[64x64]  (persistent accumulators)
// ---------------------------------------------------------------------------
__global__ __launch_bounds__(256) void out_kernel(float* __restrict__ out)
{
    extern __shared__ float sm[];
    float (*Qm)[64]  = (float(*)[64]) sm;              //  8192 floats
    float (*Qn)[64]  = (float(*)[64])(sm + 8192);      //  8192
    float (*Vs)[132] = (float(*)[132])(sm + 16384);    //  64*132 = 8448 ([n][d], padded)
    float (*Ps)[68]  = (float(*)[68])(sm + 24832);     //  64*68  = 4352 ([n][m], padded)

    const int m0 = blockIdx.x * 64;
    const int b  = blockIdx.y;
    const int tid = threadIdx.x;
    const int tx = tid & 15, ty = tid >> 4;
    const float* qkb   = g_qk  + (size_t)b * Dd * Nn;
    const float* vb    = g_v   + (size_t)b * Dd * Nn;
    const float* linvb = g_linv + (size_t)b * Nn;

    for (int i = tid; i < Dd * 16; i += 256) {
        int row = i >> 4, c4 = (i & 15) * 4;
        *(float4*)&Qm[row][c4] = *(const float4*)&qkb[row * Nn + m0 + c4];
    }
    float o[8][4] = {};
    __syncthreads();

    for (int n0 = 0; n0 < Nn; n0 += 64) {
        for (int i = tid; i < Dd * 16; i += 256) {
            int row = i >> 4, c4 = (i & 15) * 4;
            *(float4*)&Qn[row][c4] = *(const float4*)&qkb[row * Nn + n0 + c4];
            float4 v = *(const float4*)&vb[row * Nn + n0 + c4];
            Vs[c4 + 0][row] = v.x; Vs[c4 + 1][row] = v.y;
            Vs[c4 + 2][row] = v.z; Vs[c4 + 3][row] = v.w;
        }
        __syncthreads();

        // Phase A: e tile rows n = n0+ty*4+r, cols m = m0+tx*4+c
        float acc[4][4] = {};
        #pragma unroll 8
        for (int k = 0; k < Dd; ++k) {
            float a[4];
            #pragma unroll
            for (int r = 0; r < 4; ++r) a[r] = Qn[k][ty * 4 + r];
            float4 bb = *(const float4*)&Qm[k][tx * 4];
            float bv4[4] = {bb.x, bb.y, bb.z, bb.w};
            #pragma unroll
            for (int r = 0; r < 4; ++r)
                #pragma unroll
                for (int c = 0; c < 4; ++c) acc[r][c] += a[r] * bv4[c];
        }
        #pragma unroll
        for (int r = 0; r < 4; ++r) {
            float li = __ldg(&linvb[n0 + ty * 4 + r]);
            float4 p = make_float4(__expf(acc[r][0] * INV_SCALE) * li,
                                   __expf(acc[r][1] * INV_SCALE) * li,
                                   __expf(acc[r][2] * INV_SCALE) * li,
                                   __expf(acc[r][3] * INV_SCALE) * li);
            *(float4*)&Ps[ty * 4 + r][tx * 4] = p;
        }
        __syncthreads();

        // Phase B: O[d,m] += sum_kn Vs[kn][d] * Ps[kn][m]
        #pragma unroll 4
        for (int kn = 0; kn < 64; ++kn) {
            float4 v0 = *(const float4*)&Vs[kn][ty * 8];
            float4 v1 = *(const float4*)&Vs[kn][ty * 8 + 4];
            float4 pp = *(const float4*)&Ps[kn][tx * 4];
            float av8[8] = {v0.x, v0.y, v0.z, v0.w, v1.x, v1.y, v1.z, v1.w};
            float bp[4]  = {pp.x, pp.y, pp.z, pp.w};
            #pragma unroll
            for (int j = 0; j < 8; ++j)
                #pragma unroll
                for (int c = 0; c < 4; ++c) o[j][c] += av8[j] * bp[c];
        }
        __syncthreads();
    }

    #pragma unroll
    for (int j = 0; j < 8; ++j) {
        int d = ty * 8 + j;
        *(float4*)&out[((size_t)b * Dd + d) * Nn + m0 + tx * 4] =
            make_float4(o[j][0], o[j][1], o[j][2], o[j][3]);
    }
}

// ---------------------------------------------------------------------------
extern "C" void kernel_launch(void* const* d_in, const int* in_sizes, int n_in,
                              void* d_out, int out_size)
{
    const float* x   = (const float*)d_in[0];   // [8, 512, 2048]
    const float* wqk = (const float*)d_in[1];   // [128, 512]
    const float* wv  = (const float*)d_in[2];   // [128, 512]
    const float* bv  = (const float*)d_in[3];   // [128]
    float* out = (float*)d_out;                 // [8, 128, 2048]

    const int smem2 = 2 * Dd * 64 * (int)sizeof(float);                 // 65536 B
    const int smem3 = (8192 + 8192 + 64 * 132 + 64 * 68) * (int)sizeof(float); // 116736 B
    cudaFuncSetAttribute(stats_kernel, cudaFuncAttributeMaxDynamicSharedMemorySize, smem2);
    cudaFuncSetAttribute(out_kernel,   cudaFuncAttributeMaxDynamicSharedMemorySize, smem3);

    proj_kernel <<<dim3(Nn / 64, Dd / 64, Bz), 256>>>(x, wqk, wv, bv);
    stats_kernel<<<dim3(Nn / 64, Bz), 256, smem2>>>();
    out_kernel  <<<dim3(Nn / 64, Bz), 256, smem3>>>(out);
}

// round 4
// speedup vs baseline: 1.7399x; 1.7399x over previous
#include <cuda_runtime.h>

#define Bz 8
#define Cc 512
#define Nn 2048
#define Dd 128
#define INV_SCALE 0.08838834764831845f   // 1/sqrt(128)

typedef unsigned long long ull;

// Scratch (allocation-free rule: __device__ globals)
__device__ float g_qk[(size_t)Bz * Dd * Nn];     // [b][d][n]   8 MB
__device__ float g_v [(size_t)Bz * Dd * Nn];     // [b][d][n]   8 MB
__device__ float g_P [(size_t)Bz * Nn * Nn];     // [b][n][m] unnormalized exp(e), 128 MB
__device__ float g_lsum[(size_t)Bz * Nn];        // row sums
__device__ float g_linv[(size_t)Bz * Nn];        // 1 / row sum

// ---------------- packed f32x2 helpers (FFMA2: 2x fp32 FMA throughput) -----
__device__ __forceinline__ void fma2(ull& d, ull a, ull b) {
    asm("fma.rn.f32x2 %0, %1, %2, %0;" : "+l"(d) : "l"(a), "l"(b));
}
__device__ __forceinline__ ull pk2(float x) {
    ull r; asm("mov.b64 %0, {%1, %1};" : "=l"(r) : "f"(x)); return r;
}
__device__ __forceinline__ float2 upk(ull v) {
    float2 f; asm("mov.b64 {%0, %1}, %2;" : "=f"(f.x), "=f"(f.y) : "l"(v)); return f;
}

// 8x8 thread-tile inner step: acc[r][cp] += a[r] * b[2cp,2cp+1]
#define MMA8x8(AsRow, BsRow)                                                   \
    {                                                                          \
        float4 a0 = *(const float4*)&(AsRow)[ty8];                             \
        float4 a1 = *(const float4*)&(AsRow)[ty8 + 4];                         \
        ulonglong2 b01 = *(const ulonglong2*)&(BsRow)[tx8];                    \
        ulonglong2 b23 = *(const ulonglong2*)&(BsRow)[tx8 + 4];                \
        float a[8] = {a0.x, a0.y, a0.z, a0.w, a1.x, a1.y, a1.z, a1.w};         \
        _Pragma("unroll")                                                      \
        for (int r = 0; r < 8; ++r) {                                          \
            ull ad = pk2(a[r]);                                                \
            fma2(acc[r][0], ad, b01.x); fma2(acc[r][1], ad, b01.y);            \
            fma2(acc[r][2], ad, b23.x); fma2(acc[r][3], ad, b23.y);            \
        }                                                                      \
    }

// ---------------------------------------------------------------------------
// zero / inv helpers for the row-sum split
// ---------------------------------------------------------------------------
__global__ void zero_kernel() {
    int i = blockIdx.x * 1024 + threadIdx.x;
    if (i < Bz * Nn) g_lsum[i] = 0.0f;
}
__global__ void inv_kernel() {
    int i = blockIdx.x * 1024 + threadIdx.x;
    if (i < Bz * Nn) g_linv[i] = 1.0f / g_lsum[i];
}

// ---------------------------------------------------------------------------
// Kernel 1: projections. Block computes a 128(d) x 128(n) tile of qk OR v.
// A = W (transposed on load), B = x.  grid (16 nT, 2 which, 8 b)
// ---------------------------------------------------------------------------
__global__ __launch_bounds__(256, 2) void proj2_kernel(
    const float* __restrict__ x, const float* __restrict__ wqk,
    const float* __restrict__ wv, const float* __restrict__ bv)
{
    __shared__ float As[32][132];   // [k=c][d], padded
    __shared__ float Bs[32][128];   // [k=c][n]
    const int n0 = blockIdx.x * 128;
    const int which = blockIdx.y;
    const int b = blockIdx.z;
    const float* W = which ? wv : wqk;
    const int tid = threadIdx.x;
    const int tx8 = (tid & 15) * 8, ty8 = (tid >> 4) * 8;
    const float* xb = x + (size_t)b * Cc * Nn;

    ull acc[8][4] = {};

    for (int c0 = 0; c0 < Cc; c0 += 32) {
        #pragma unroll
        for (int q = 0; q < 4; ++q) {
            int e = tid + q * 256;
            {   // W transpose: As[kk][dd] <- W[dd][c0+kk]
                int dd = e & 127, k4 = (e >> 7) << 2;
                float4 w4 = *(const float4*)&W[dd * Cc + c0 + k4];
                As[k4 + 0][dd] = w4.x; As[k4 + 1][dd] = w4.y;
                As[k4 + 2][dd] = w4.z; As[k4 + 3][dd] = w4.w;
            }
            {   // x direct: Bs[kk][nn]
                int kk = e >> 5, nn4 = (e & 31) * 4;
                *(float4*)&Bs[kk][nn4] =
                    *(const float4*)&xb[(c0 + kk) * Nn + n0 + nn4];
            }
        }
        __syncthreads();
        #pragma unroll
        for (int kk = 0; kk < 32; ++kk) MMA8x8(As[kk], Bs[kk]);
        __syncthreads();
    }

    float* dst = which ? g_v : g_qk;
    #pragma unroll
    for (int r = 0; r < 8; ++r) {
        int d = ty8 + r;
        float add = which ? bv[d] : 0.0f;
        float2 c0 = upk(acc[r][0]), c1 = upk(acc[r][1]);
        float2 c2 = upk(acc[r][2]), c3 = upk(acc[r][3]);
        size_t o = ((size_t)b * Dd + d) * Nn + n0 + tx8;
        *(float4*)&dst[o]     = make_float4(c0.x + add, c0.y + add, c1.x + add, c1.y + add);
        *(float4*)&dst[o + 4] = make_float4(c2.x + add, c2.y + add, c3.x + add, c3.y + add);
    }
}

// ---------------------------------------------------------------------------
// Kernel 2: energy tile e = Qn^T Qm (K = D = 128), P = exp(e/scale) stored to
// gmem, row sums accumulated to g_lsum. Block: 128 n-rows x 8 m-tiles (half
// of m range).  grid (16 nT, 2 mHalf, 8 b)
// ---------------------------------------------------------------------------
__global__ __launch_bounds__(256, 2) void stats2_kernel()
{
    extern __shared__ float sm[];
    float (*Qn)[128] = (float(*)[128])sm;               // [k=d 128][n 128], 64KB
    float (*Bs)[128] = (float(*)[128])(sm + 128 * 128); // [k 32][m 128], 16KB
    __shared__ float lsum[128];

    const int n0 = blockIdx.x * 128;
    const int mbase = blockIdx.y * (Nn / 2);
    const int b = blockIdx.z;
    const int tid = threadIdx.x;
    const int tx8 = (tid & 15) * 8, ty8 = (tid >> 4) * 8;
    const float* qkb = g_qk + (size_t)b * Dd * Nn;
    float* Pb = g_P + (size_t)b * Nn * Nn;

    #pragma unroll
    for (int q = 0; q < 16; ++q) {
        int e = tid + q * 256;
        int kd = e >> 5, nn4 = (e & 31) * 4;
        *(float4*)&Qn[kd][nn4] = *(const float4*)&qkb[kd * Nn + n0 + nn4];
    }
    if (tid < 128) lsum[tid] = 0.0f;
    float rsum[8] = {};
    __syncthreads();

    for (int mt = 0; mt < 8; ++mt) {
        const int m0 = mbase + mt * 128;
        ull acc[8][4] = {};
        for (int k0 = 0; k0 < Dd; k0 += 32) {
            #pragma unroll
            for (int q = 0; q < 4; ++q) {
                int e = tid + q * 256;
                int kk = e >> 5, mm4 = (e & 31) * 4;
                *(float4*)&Bs[kk][mm4] =
                    *(const float4*)&qkb[(k0 + kk) * Nn + m0 + mm4];
            }
            __syncthreads();
            #pragma unroll
            for (int kk = 0; kk < 32; ++kk) MMA8x8(Qn[k0 + kk], Bs[kk]);
            __syncthreads();
        }
        // epilogue: exp, row-sum, store P tile
        #pragma unroll
        for (int r = 0; r < 8; ++r) {
            float p[8];
            #pragma unroll
            for (int cp = 0; cp < 4; ++cp) {
                float2 e2 = upk(acc[r][cp]);
                p[2 * cp]     = __expf(e2.x * INV_SCALE);
                p[2 * cp + 1] = __expf(e2.y * INV_SCALE);
                rsum[r] += p[2 * cp] + p[2 * cp + 1];
            }
            size_t row = (size_t)(n0 + ty8 + r) * Nn + m0 + tx8;
            *(float4*)&Pb[row]     = make_float4(p[0], p[1], p[2], p[3]);
            *(float4*)&Pb[row + 4] = make_float4(p[4], p[5], p[6], p[7]);
        }
    }

    #pragma unroll
    for (int r = 0; r < 8; ++r) atomicAdd(&lsum[ty8 + r], rsum[r]);
    __syncthreads();
    if (tid < 128)
        atomicAdd(&g_lsum[(size_t)b * Nn + n0 + tid], lsum[tid]);
}

// ---------------------------------------------------------------------------
// Kernel 3: pure SGEMM  out[d, m] = sum_n (v[d,n] * linv[n]) * P[n, m]
// Block: 128 d x 128 m, K = N = 2048 in 32-chunks.  grid (16 mT, 8 b)
// ---------------------------------------------------------------------------
__global__ __launch_bounds__(256, 2) void out2_kernel(float* __restrict__ out)
{
    __shared__ float As[32][132];   // [k=n][d], V transposed (unscaled)
    __shared__ float Bs[32][128];   // [k=n][m], P scaled by linv[n]
    const int m0 = blockIdx.x * 128;
    const int b = blockIdx.y;
    const int tid = threadIdx.x;
    const int tx8 = (tid & 15) * 8, ty8 = (tid >> 4) * 8;
    const float* vb = g_v + (size_t)b * Dd * Nn;
    const float* linvb = g_linv + (size_t)b * Nn;
    const float* Pb = g_P + (size_t)b * Nn * Nn;

    ull acc[8][4] = {};

    for (int n0 = 0; n0 < Nn; n0 += 32) {
        #pragma unroll
        for (int q = 0; q < 4; ++q) {
            int e = tid + q * 256;
            {   // V transpose: As[kk][dd] <- v[dd][n0+kk]
                int dd = e & 127, k4 = (e >> 7) << 2;
                float4 vv = *(const float4*)&vb[dd * Nn + n0 + k4];
                As[k4 + 0][dd] = vv.x; As[k4 + 1][dd] = vv.y;
                As[k4 + 2][dd] = vv.z; As[k4 + 3][dd] = vv.w;
            }
            {   // P direct, scaled by linv
                int kk = e >> 5, mm4 = (e & 31) * 4;
                float li = __ldg(&linvb[n0 + kk]);
                float4 p = *(const float4*)&Pb[(size_t)(n0 + kk) * Nn + m0 + mm4];
                *(float4*)&Bs[kk][mm4] =
                    make_float4(p.x * li, p.y * li, p.z * li, p.w * li);
            }
        }
        __syncthreads();
        #pragma unroll
        for (int kk = 0; kk < 32; ++kk) MMA8x8(As[kk], Bs[kk]);
        __syncthreads();
    }

    #pragma unroll
    for (int r = 0; r < 8; ++r) {
        int d = ty8 + r;
        float2 c0 = upk(acc[r][0]), c1 = upk(acc[r][1]);
        float2 c2 = upk(acc[r][2]), c3 = upk(acc[r][3]);
        size_t o = ((size_t)b * Dd + d) * Nn + m0 + tx8;
        *(float4*)&out[o]     = make_float4(c0.x, c0.y, c1.x, c1.y);
        *(float4*)&out[o + 4] = make_float4(c2.x, c2.y, c3.x, c3.y);
    }
}

// ---------------------------------------------------------------------------
extern "C" void kernel_launch(void* const* d_in, const int* in_sizes, int n_in,
                              void* d_out, int out_size)
{
    const float* x   = (const float*)d_in[0];   // [8, 512, 2048]
    const float* wqk = (const float*)d_in[1];   // [128, 512]
    const float* wv  = (const float*)d_in[2];   // [128, 512]
    const float* bv  = (const float*)d_in[3];   // [128]
    float* out = (float*)d_out;                 // [8, 128, 2048]

    const int smemS = (128 * 128 + 32 * 128) * (int)sizeof(float);  // 81920 B
    static int configured = 0;
    cudaFuncSetAttribute(stats2_kernel,
                         cudaFuncAttributeMaxDynamicSharedMemorySize, smemS);
    (void)configured;

    zero_kernel <<<16, 1024>>>();
    proj2_kernel<<<dim3(Nn / 128, 2, Bz), 256>>>(x, wqk, wv, bv);
    stats2_kernel<<<dim3(Nn / 128, 2, Bz), 256, smemS>>>();
    inv_kernel  <<<16, 1024>>>();
    out2_kernel <<<dim3(Nn / 128, Bz), 256>>>(out);
}

// round 13
// speedup vs baseline: 1.8561x; 1.0668x over previous
#include <cuda_runtime.h>

#define Bz 8
#define Cc 512
#define Nn 2048
#define Dd 128
#define INV_SCALE 0.08838834764831845f   // 1/sqrt(128)

typedef unsigned long long ull;
typedef unsigned int u32;

// ------------------------- scratch (__device__ globals) --------------------
__device__ float g_qk [(size_t)Bz * Dd * Nn];   // [b][d][n]  8 MB
__device__ float g_v  [(size_t)Bz * Dd * Nn];   // [b][d][n]  8 MB
__device__ float g_vT [(size_t)Bz * Nn * Dd];   // [b][n][d] = v*linv  8 MB
__device__ float g_wT [2 * Cc * Dd];            // W transposed [which][c][d]
__device__ float g_P  [(size_t)Bz * Nn * Nn];   // exp(e) unnormalized, 128 MB
__device__ float g_lsum[Bz * Nn];
__device__ float g_linv[Bz * Nn];

// ------------------------- helpers -----------------------------------------
__device__ __forceinline__ u32 smem_u32(const void* p) {
    u32 a;
    asm("{ .reg .u64 t; cvta.to.shared.u64 t, %1; cvt.u32.u64 %0, t; }"
        : "=r"(a) : "l"(p));
    return a;
}
__device__ __forceinline__ void cp16(u32 dst, const void* src) {
    asm volatile("cp.async.ca.shared.global [%0], [%1], 16;"
                 :: "r"(dst), "l"(src));
}
#define CP_COMMIT() asm volatile("cp.async.commit_group;" ::: "memory")
#define CP_WAIT(n)  asm volatile("cp.async.wait_group %0;" :: "n"(n) : "memory")

__device__ __forceinline__ void fma2(ull& d, ull a, ull b) {
    asm("fma.rn.f32x2 %0, %1, %2, %0;" : "+l"(d) : "l"(a), "l"(b));
}
__device__ __forceinline__ ull pk2(float x) {
    ull r; asm("mov.b64 %0, {%1, %1};" : "=l"(r) : "f"(x)); return r;
}
__device__ __forceinline__ float2 upk(ull v) {
    float2 f; asm("mov.b64 {%0, %1}, %2;" : "=f"(f.x), "=f"(f.y) : "l"(v)); return f;
}

// 8x8 thread tile (256 thr -> 128x128 CTA tile). Ap/Bp point at one k-row.
#define MMA8x8(Ap, Bp)                                                         \
    {                                                                          \
        float4 a0 = *(const float4*)&(Ap)[ty8];                                \
        float4 a1 = *(const float4*)&(Ap)[ty8 + 4];                            \
        ulonglong2 b01 = *(const ulonglong2*)&(Bp)[tx8];                       \
        ulonglong2 b23 = *(const ulonglong2*)&(Bp)[tx8 + 4];                   \
        float a[8] = {a0.x, a0.y, a0.z, a0.w, a1.x, a1.y, a1.z, a1.w};         \
        _Pragma("unroll")                                                      \
        for (int r = 0; r < 8; ++r) {                                          \
            ull ad = pk2(a[r]);                                                \
            fma2(acc[r][0], ad, b01.x); fma2(acc[r][1], ad, b01.y);            \
            fma2(acc[r][2], ad, b23.x); fma2(acc[r][3], ad, b23.y);            \
        }                                                                      \
    }

// 4x8 thread tile (256 thr -> 128x64 CTA tile)
#define MMA4x8(Ap, Bp)                                                         \
    {                                                                          \
        float4 a0 = *(const float4*)&(Ap)[ty4];                                \
        ulonglong2 b01 = *(const ulonglong2*)&(Bp)[tx8];                       \
        ulonglong2 b23 = *(const ulonglong2*)&(Bp)[tx8 + 4];                   \
        float a[4] = {a0.x, a0.y, a0.z, a0.w};                                 \
        _Pragma("unroll")                                                      \
        for (int r = 0; r < 4; ++r) {                                          \
            ull ad = pk2(a[r]);                                                \
            fma2(acc[r][0], ad, b01.x); fma2(acc[r][1], ad, b01.y);            \
            fma2(acc[r][2], ad, b23.x); fma2(acc[r][3], ad, b23.y);            \
        }                                                                      \
    }

// ---------------------------------------------------------------------------
// tiny helpers
// ---------------------------------------------------------------------------
__global__ void zero_kernel() {
    int i = blockIdx.x * 1024 + threadIdx.x;
    if (i < Bz * Nn) g_lsum[i] = 0.0f;
}
__global__ void inv_kernel() {
    int i = blockIdx.x * 1024 + threadIdx.x;
    if (i < Bz * Nn) g_linv[i] = 1.0f / g_lsum[i];
}
// transpose weights: g_wT[which][c][d] = W[d][c]
__global__ void k_wT(const float* __restrict__ wqk, const float* __restrict__ wv) {
    __shared__ float T[32][33];
    const int ct = blockIdx.x, dt = blockIdx.y, which = blockIdx.z;
    const float* W = which ? wv : wqk;
    float* WT = g_wT + which * Cc * Dd;
    const int tx = threadIdx.x, ty = threadIdx.y;
    for (int yy = ty; yy < 32; yy += 8)
        T[yy][tx] = W[(dt * 32 + yy) * Cc + ct * 32 + tx];
    __syncthreads();
    for (int yy = ty; yy < 32; yy += 8)
        WT[(ct * 32 + yy) * Dd + dt * 32 + tx] = T[tx][yy];
}
// vT[n][d] = v[d][n] * linv[n]
__global__ void k_vT() {
    __shared__ float T[32][33];
    const int nt = blockIdx.x, dt = blockIdx.y, b = blockIdx.z;
    const float* vb = g_v + (size_t)b * Dd * Nn;
    float* vTb = g_vT + (size_t)b * Nn * Dd;
    const float* linvb = g_linv + b * Nn;
    const int tx = threadIdx.x, ty = threadIdx.y;
    for (int yy = ty; yy < 32; yy += 8)
        T[yy][tx] = vb[(size_t)(dt * 32 + yy) * Nn + nt * 32 + tx];
    __syncthreads();
    for (int yy = ty; yy < 32; yy += 8)
        vTb[(size_t)(nt * 32 + yy) * Dd + dt * 32 + tx] =
            T[tx][yy] * linvb[nt * 32 + yy];
}

// ---------------------------------------------------------------------------
// Kernel 1: projections, cp.async double-buffered.
// 128(d) x 128(n) tile; A = WT [c][d] direct, B = x [c][n] direct.
// ---------------------------------------------------------------------------
__global__ __launch_bounds__(256, 2) void proj3(
    const float* __restrict__ x, const float* __restrict__ bv)
{
    extern __shared__ float sm[];
    float* bufA = sm;          // 2 x 32x128
    float* bufB = sm + 8192;   // 2 x 32x128
    const int n0 = blockIdx.x * 128, which = blockIdx.y, b = blockIdx.z;
    const int tid = threadIdx.x;
    const int tx8 = (tid & 15) * 8, ty8 = (tid >> 4) * 8;
    const float* WT = g_wT + which * Cc * Dd;
    const float* xb = x + (size_t)b * Cc * Nn;
    const u32 sA = smem_u32(bufA), sB = smem_u32(bufB);

    ull acc[8][4] = {};

#define PROJ_ISSUE(c0, buf)                                                    \
    {                                                                          \
        u32 dA = sA + (buf) * 16384, dB = sB + (buf) * 16384;                  \
        _Pragma("unroll")                                                      \
        for (int q = 0; q < 4; ++q) {                                          \
            int slot = tid + q * 256;                                          \
            int row = slot >> 5, col4 = (slot & 31) * 4;                       \
            cp16(dA + slot * 16, WT + ((c0) + row) * Dd + col4);               \
            cp16(dB + slot * 16, xb + (size_t)((c0) + row) * Nn + n0 + col4);  \
        }                                                                      \
        CP_COMMIT();                                                           \
    }

    PROJ_ISSUE(0, 0);
    for (int c = 0; c < 16; ++c) {
        if (c + 1 < 16) { PROJ_ISSUE((c + 1) * 32, (c + 1) & 1); CP_WAIT(1); }
        else            { CP_WAIT(0); }
        __syncthreads();
        const float* A = bufA + (c & 1) * 4096;
        const float* B = bufB + (c & 1) * 4096;
        #pragma unroll
        for (int kk = 0; kk < 32; ++kk) MMA8x8(A + kk * 128, B + kk * 128);
        __syncthreads();
    }

    float* dst = which ? g_v : g_qk;
    #pragma unroll
    for (int r = 0; r < 8; ++r) {
        int d = ty8 + r;
        float add = which ? bv[d] : 0.0f;
        float2 c0 = upk(acc[r][0]), c1 = upk(acc[r][1]);
        float2 c2 = upk(acc[r][2]), c3 = upk(acc[r][3]);
        size_t o = ((size_t)b * Dd + d) * Nn + n0 + tx8;
        *(float4*)&dst[o]     = make_float4(c0.x + add, c0.y + add, c1.x + add, c1.y + add);
        *(float4*)&dst[o + 4] = make_float4(c2.x + add, c2.y + add, c3.x + add, c3.y + add);
    }
}

// ---------------------------------------------------------------------------
// Kernel 2: symmetric stats. Only upper-triangular tile pairs (i<=j): 136/256.
// e-tile = qk[:,n-range]^T qk[:,m-range] (K=128); P written both orientations;
// row sums (and col sums for off-diagonal) atomically into g_lsum.
// ---------------------------------------------------------------------------
__global__ __launch_bounds__(256, 2) void stats4()
{
    extern __shared__ float sm[];
    float* bufA = sm;          // 2 x 32x128
    float* bufB = sm + 8192;
    __shared__ float lsumS[128], csumS[128];

    int idx = blockIdx.x;
    const int b = blockIdx.y;
    int i = 0;
    while (idx >= 16 - i) { idx -= 16 - i; ++i; }
    const int j = i + idx;
    const int n0 = i * 128, m0 = j * 128;
    const bool diag = (i == j);

    const int tid = threadIdx.x;
    const int tx8 = (tid & 15) * 8, ty8 = (tid >> 4) * 8;
    const float* qkb = g_qk + (size_t)b * Dd * Nn;
    float* Pb = g_P + (size_t)b * Nn * Nn;
    const u32 sA = smem_u32(bufA), sB = smem_u32(bufB);

    if (tid < 128) { lsumS[tid] = 0.0f; csumS[tid] = 0.0f; }

    ull acc[8][4] = {};

#define STATS_ISSUE(c0, buf)                                                   \
    {                                                                          \
        u32 dA = sA + (buf) * 16384, dB = sB + (buf) * 16384;                  \
        _Pragma("unroll")                                                      \
        for (int q = 0; q < 4; ++q) {                                          \
            int slot = tid + q * 256;                                          \
            int row = slot >> 5, col4 = (slot & 31) * 4;                       \
            cp16(dA + slot * 16, qkb + (size_t)((c0) + row) * Nn + n0 + col4); \
            cp16(dB + slot * 16, qkb + (size_t)((c0) + row) * Nn + m0 + col4); \
        }                                                                      \
        CP_COMMIT();                                                           \
    }

    STATS_ISSUE(0, 0);
    for (int c = 0; c < 4; ++c) {
        if (c + 1 < 4) { STATS_ISSUE((c + 1) * 32, (c + 1) & 1); CP_WAIT(1); }
        else           { CP_WAIT(0); }
        __syncthreads();
        const float* A = bufA + (c & 1) * 4096;
        const float* B = bufB + (c & 1) * 4096;
        #pragma unroll
        for (int kk = 0; kk < 32; ++kk) MMA8x8(A + kk * 128, B + kk * 128);
        __syncthreads();
    }

    // epilogue
    float p[8][8];
    #pragma unroll
    for (int r = 0; r < 8; ++r)
        #pragma unroll
        for (int c = 0; c < 4; ++c) {
            float2 e2 = upk(acc[r][c]);
            p[r][2 * c]     = __expf(e2.x * INV_SCALE);
            p[r][2 * c + 1] = __expf(e2.y * INV_SCALE);
        }

    #pragma unroll
    for (int r = 0; r < 8; ++r) {
        float rs = 0.0f;
        #pragma unroll
        for (int c = 0; c < 8; ++c) rs += p[r][c];
        atomicAdd(&lsumS[ty8 + r], rs);
        size_t rb = (size_t)(n0 + ty8 + r) * Nn + m0 + tx8;
        *(float4*)&Pb[rb]     = make_float4(p[r][0], p[r][1], p[r][2], p[r][3]);
        *(float4*)&Pb[rb + 4] = make_float4(p[r][4], p[r][5], p[r][6], p[r][7]);
    }
    if (!diag) {
        #pragma unroll
        for (int c = 0; c < 8; ++c) {
            float cs = p[0][c] + p[1][c] + p[2][c] + p[3][c]
                     + p[4][c] + p[5][c] + p[6][c] + p[7][c];
            atomicAdd(&csumS[tx8 + c], cs);
            size_t rb = (size_t)(m0 + tx8 + c) * Nn + n0 + ty8;
            *(float4*)&Pb[rb]     = make_float4(p[0][c], p[1][c], p[2][c], p[3][c]);
            *(float4*)&Pb[rb + 4] = make_float4(p[4][c], p[5][c], p[6][c], p[7][c]);
        }
    }
    __syncthreads();
    if (tid < 128) {
        atomicAdd(&g_lsum[b * Nn + n0 + tid], lsumS[tid]);
        if (!diag) atomicAdd(&g_lsum[b * Nn + m0 + tid], csumS[tid]);
    }
}

// ---------------------------------------------------------------------------
// Kernel 3: out[d][m] = sum_n vT[n][d] * P[n][m].  K = 2048, 64 chunks of 32,
// cp.async double-buffered. CTA tile 128(d) x 64(m), thread tile 4x8.
// ---------------------------------------------------------------------------
__global__ __launch_bounds__(256, 2) void out4(float* __restrict__ out)
{
    extern __shared__ float sm[];
    float* bufA = sm;          // 2 x 32x128 (vT chunk)
    float* bufB = sm + 8192;   // 2 x 32x64  (P chunk)
    const int m0 = blockIdx.x * 64, b = blockIdx.y;
    const int tid = threadIdx.x;
    const int tx8 = (tid & 7) * 8, ty4 = (tid >> 3) * 4;
    const float* vTb = g_vT + (size_t)b * Nn * Dd;
    const float* Pb  = g_P  + (size_t)b * Nn * Nn;
    const u32 sA = smem_u32(bufA), sB = smem_u32(bufB);

    ull acc[4][4] = {};

#define OUT_ISSUE(nc, buf)                                                     \
    {                                                                          \
        u32 dA = sA + (buf) * 16384, dB = sB + (buf) * 8192;                   \
        _Pragma("unroll")                                                      \
        for (int q = 0; q < 4; ++q) {                                          \
            int slot = tid + q * 256;                                          \
            int row = slot >> 5, col4 = (slot & 31) * 4;                       \
            cp16(dA + slot * 16, vTb + (size_t)((nc) + row) * Dd + col4);      \
        }                                                                      \
        _Pragma("unroll")                                                      \
        for (int q = 0; q < 2; ++q) {                                          \
            int slot = tid + q * 256;                                          \
            int row = slot >> 4, col4 = (slot & 15) * 4;                       \
            cp16(dB + slot * 16, Pb + (size_t)((nc) + row) * Nn + m0 + col4);  \
        }                                                                      \
        CP_COMMIT();                                                           \
    }

    OUT_ISSUE(0, 0);
    for (int c = 0; c < 64; ++c) {
        if (c + 1 < 64) { OUT_ISSUE((c + 1) * 32, (c + 1) & 1); CP_WAIT(1); }
        else            { CP_WAIT(0); }
        __syncthreads();
        const float* A = bufA + (c & 1) * 4096;
        const float* B = bufB + (c & 1) * 2048;
        #pragma unroll
        for (int kk = 0; kk < 32; ++kk) MMA4x8(A + kk * 128, B + kk * 64);
        __syncthreads();
    }

    #pragma unroll
    for (int r = 0; r < 4; ++r) {
        int d = ty4 + r;
        float2 c0 = upk(acc[r][0]), c1 = upk(acc[r][1]);
        float2 c2 = upk(acc[r][2]), c3 = upk(acc[r][3]);
        size_t o = ((size_t)b * Dd + d) * Nn + m0 + tx8;
        *(float4*)&out[o]     = make_float4(c0.x, c0.y, c1.x, c1.y);
        *(float4*)&out[o + 4] = make_float4(c2.x, c2.y, c3.x, c3.y);
    }
}

// ---------------------------------------------------------------------------
extern "C" void kernel_launch(void* const* d_in, const int* in_sizes, int n_in,
                              void* d_out, int out_size)
{
    const float* x   = (const float*)d_in[0];   // [8, 512, 2048]
    const float* wqk = (const float*)d_in[1];   // [128, 512]
    const float* wv  = (const float*)d_in[2];   // [128, 512]
    const float* bv  = (const float*)d_in[3];   // [128]
    float* out = (float*)d_out;                 // [8, 128, 2048]

    cudaFuncSetAttribute(proj3,  cudaFuncAttributeMaxDynamicSharedMemorySize, 65536);
    cudaFuncSetAttribute(stats4, cudaFuncAttributeMaxDynamicSharedMemorySize, 65536);
    cudaFuncSetAttribute(out4,   cudaFuncAttributeMaxDynamicSharedMemorySize, 49152);

    k_wT        <<<dim3(Cc / 32, Dd / 32, 2), dim3(32, 8)>>>(wqk, wv);
    zero_kernel <<<16, 1024>>>();
    proj3       <<<dim3(Nn / 128, 2, Bz), 256, 65536>>>(x, bv);
    stats4      <<<dim3(136, Bz), 256, 65536>>>();
    inv_kernel  <<<16, 1024>>>();
    k_vT        <<<dim3(Nn / 32, Dd / 32, Bz), dim3(32, 8)>>>();
    out4        <<<dim3(Nn / 64, Bz), 256, 49152>>>(out);
}